// round 3
// baseline (speedup 1.0000x reference)
#include <cuda_runtime.h>
#include <cuda_fp16.h>
#include <cstdint>
#include <cstddef>

// ============================================================================
// KAN layer as one fp16 GEMM (portable sm_100 path: cp.async + ldmatrix +
// mma.sync.m16n8k16 — NO tcgen05, which plain sm_100 target rejects):
//   out[m,o] = sum_i x[m,i]*Wb[o,i] + sum_j hat_j(clamp(x))*T_j[o,i]
// A: (8192 x 7168) fp16 row-major, 7 cols per input (x, hat0..hat5)
// W: (1024 x 7168) fp16 row-major, (Wb, T0..T5); the 12-knot tent basis
// collapses to 6 distinct knots: T0=S0+..+S3, T1..4=S4..7, T5=S8+..+S11.
// GEMM: C = A @ W^T, fp32 accum in registers.
// ============================================================================

#define INF_   1024
#define OUTF_  1024
#define MTOT   8192
#define KD     7168            // 7 * 1024
#define BM     128
#define BN     128
#define BK     64
#define KT     (KD / BK)       // 112
#define STG    3
#define ASZ    (BM * BK * 2)   // 16384
#define BSZ    (BN * BK * 2)   // 16384
#define STAGEB (ASZ + BSZ)     // 32768
#define SMEMSZ (STG * STAGEB)  // 98304

__device__ __align__(16) __half g_A[(size_t)MTOT * KD];   // 112 MB
__device__ __align__(16) __half g_W[(size_t)OUTF_ * KD];  // 14 MB

// ---------------------------------------------------------------------------
// helpers
// ---------------------------------------------------------------------------
__device__ __forceinline__ uint32_t s2u(const void* p) {
    uint32_t a;
    asm("{ .reg .u64 t; cvta.to.shared.u64 t, %1; cvt.u32.u64 %0, t; }"
        : "=r"(a) : "l"(p));
    return a;
}
__device__ __forceinline__ void cpasync16(uint32_t dst, const void* src) {
    asm volatile("cp.async.cg.shared.global [%0], [%1], 16;" :: "r"(dst), "l"(src));
}
__device__ __forceinline__ void ldsm4(uint32_t* r, uint32_t a) {
    asm volatile("ldmatrix.sync.aligned.m8n8.x4.shared.b16 {%0,%1,%2,%3}, [%4];"
                 : "=r"(r[0]), "=r"(r[1]), "=r"(r[2]), "=r"(r[3]) : "r"(a));
}
__device__ __forceinline__ void mma16816(float* c, const uint32_t* a, const uint32_t* b) {
    asm volatile(
        "mma.sync.aligned.m16n8k16.row.col.f32.f16.f16.f32 "
        "{%0,%1,%2,%3}, {%4,%5,%6,%7}, {%8,%9}, {%0,%1,%2,%3};"
        : "+f"(c[0]), "+f"(c[1]), "+f"(c[2]), "+f"(c[3])
        : "r"(a[0]), "r"(a[1]), "r"(a[2]), "r"(a[3]), "r"(b[0]), "r"(b[1]));
}

// ---------------------------------------------------------------------------
// Prologue 1: build A fp16 row-major from x.  k = i*7 + c.
//   c==0 -> x ; c=1..6 -> relu(1 - 2.5*|clamp(x) - (-1 + 0.4*(c-1))|)
// ---------------------------------------------------------------------------
__global__ void __launch_bounds__(256) build_A(const float* __restrict__ x) {
    int u = blockIdx.x * 256 + threadIdx.x;          // one 16B chunk (8 halves)
    int m = u / (KD / 8);
    int k0 = (u - m * (KD / 8)) * 8;
    const float* xr = x + (size_t)m * INF_;
    union { __half h[8]; uint4 v; } pk;
    #pragma unroll
    for (int j = 0; j < 8; j++) {
        int k = k0 + j;
        int i = k / 7;
        int c = k - i * 7;
        float xv = xr[i];
        float a;
        if (c == 0) {
            a = xv;
        } else {
            float xc = fminf(fmaxf(xv, -1.0f), 1.0f);
            float p = 0.4f * (float)(c - 1) - 1.0f;
            a = fmaxf(0.0f, 1.0f - fabsf(xc - p) * 2.5f);
        }
        pk.h[j] = __float2half_rn(a);
    }
    *reinterpret_cast<uint4*>(reinterpret_cast<char*>(g_A) + (size_t)u * 16) = pk.v;
}

// ---------------------------------------------------------------------------
// Prologue 2: build W fp16 row-major.
//   c==0 -> base_weight ; c==1 -> S0+S1+S2+S3 ; c==6 -> S8+..+S11 ; else S[c+2]
// ---------------------------------------------------------------------------
__global__ void __launch_bounds__(256) build_W(const float* __restrict__ sw,
                                               const float* __restrict__ bw) {
    int u = blockIdx.x * 256 + threadIdx.x;
    int o = u / (KD / 8);
    int k0 = (u - o * (KD / 8)) * 8;
    union { __half h[8]; uint4 v; } pk;
    #pragma unroll
    for (int j = 0; j < 8; j++) {
        int k = k0 + j;
        int i = k / 7;
        int c = k - i * 7;
        float v;
        if (c == 0) {
            v = bw[(size_t)o * INF_ + i];
        } else {
            const float* s = sw + ((size_t)o * INF_ + i) * 12;
            if (c == 1)      v = s[0] + s[1] + s[2] + s[3];
            else if (c == 6) v = s[8] + s[9] + s[10] + s[11];
            else             v = s[c + 2];   // c=2..5 -> S4..S7
        }
        pk.h[j] = __float2half_rn(v);
    }
    *reinterpret_cast<uint4*>(reinterpret_cast<char*>(g_W) + (size_t)u * 16) = pk.v;
}

// ---------------------------------------------------------------------------
// GEMM: out = A(8192x7168) @ W(1024x7168)^T, fp16 in, fp32 reg accum.
// CTA 128x128x64, 3-stage cp.async pipeline, XOR-swizzled SMEM, 8 warps 4Mx2N,
// warp tile 32x64 (2 m16 x 8 n8 tiles), mma.m16n8k16.
// ---------------------------------------------------------------------------
__global__ void __launch_bounds__(256, 2) kan_gemm(float* __restrict__ out) {
    extern __shared__ unsigned char smem[];
    uint32_t sb = s2u(smem);
    int tid = threadIdx.x;
    int wid = tid >> 5, lid = tid & 31;
    int m0 = blockIdx.x * BM;
    int n0 = blockIdx.y * BN;

    const char* aG = reinterpret_cast<const char*>(g_A) + (size_t)m0 * (KD * 2);
    const char* bG = reinterpret_cast<const char*>(g_W) + (size_t)n0 * (KD * 2);

    // per-thread cp.async coordinates (4 chunks of A + 4 of B per stage)
    int ldRow[4], ldCol[4];
    #pragma unroll
    for (int j = 0; j < 4; j++) {
        int id = tid + j * 256;
        ldRow[j] = id >> 3;
        ldCol[j] = id & 7;
    }

    #define LOAD_STAGE(s, it)                                                          \
        do {                                                                           \
            uint32_t base_ = sb + (s) * STAGEB;                                        \
            const char* ga_ = aG + (size_t)(it) * 128;                                 \
            const char* gb_ = bG + (size_t)(it) * 128;                                 \
            _Pragma("unroll")                                                          \
            for (int j = 0; j < 4; j++) {                                              \
                int r_ = ldRow[j], c_ = ldCol[j];                                      \
                cpasync16(base_ + r_ * 128 + ((c_ ^ (r_ & 7)) << 4),                   \
                          ga_ + (size_t)r_ * (KD * 2) + c_ * 16);                      \
            }                                                                          \
            _Pragma("unroll")                                                          \
            for (int j = 0; j < 4; j++) {                                              \
                int r_ = ldRow[j], c_ = ldCol[j];                                      \
                cpasync16(base_ + ASZ + r_ * 128 + ((c_ ^ (r_ & 7)) << 4),             \
                          gb_ + (size_t)r_ * (KD * 2) + c_ * 16);                      \
            }                                                                          \
            asm volatile("cp.async.commit_group;");                                    \
        } while (0)

    int wm = (wid >> 1) * 32;   // warp M offset (4 warps)
    int wn = (wid & 1) * 64;    // warp N offset (2 warps)

    float acc[2][8][4] = {};

    LOAD_STAGE(0, 0);
    LOAD_STAGE(1, 1);

    // precompute ldmatrix lane geometry
    int mi = lid >> 3;            // matrix index within x4
    int lr = lid & 7;             // row within 8x8 matrix

    for (int it = 0; it < KT; ++it) {
        if (it + 1 < KT) asm volatile("cp.async.wait_group 1;");
        else             asm volatile("cp.async.wait_group 0;");
        __syncthreads();
        if (it + 2 < KT) LOAD_STAGE((it + 2) % STG, it + 2);

        uint32_t asB = sb + (it % STG) * STAGEB;
        uint32_t bsB = asB + ASZ;

        #pragma unroll
        for (int ks = 0; ks < 4; ++ks) {
            uint32_t aF[2][4], bF[4][4];
            #pragma unroll
            for (int a = 0; a < 2; a++) {
                int mr = wm + a * 16 + lr + (mi & 1) * 8;
                int kc = ks * 2 + (mi >> 1);            // 16B chunk index
                ldsm4(aF[a], asB + mr * 128 + ((kc ^ (mr & 7)) << 4));
            }
            #pragma unroll
            for (int p = 0; p < 4; p++) {
                int nr = wn + p * 16 + ((mi >> 1) << 3) + lr;
                int kc = ks * 2 + (mi & 1);
                ldsm4(bF[p], bsB + nr * 128 + ((kc ^ (nr & 7)) << 4));
            }
            #pragma unroll
            for (int a = 0; a < 2; a++)
                #pragma unroll
                for (int b = 0; b < 8; b++)
                    mma16816(acc[a][b], aF[a], &bF[b >> 1][(b & 1) * 2]);
        }
    }

    // epilogue: fp32 register tiles -> gmem
    int row0 = m0 + wm + (lid >> 2);
    int col0 = n0 + wn + (lid & 3) * 2;
    #pragma unroll
    for (int a = 0; a < 2; a++) {
        #pragma unroll
        for (int b = 0; b < 8; b++) {
            float* p0 = out + (size_t)(row0 + a * 16) * OUTF_ + col0 + b * 8;
            float* p1 = p0 + (size_t)8 * OUTF_;
            *reinterpret_cast<float2*>(p0) = make_float2(acc[a][b][0], acc[a][b][1]);
            *reinterpret_cast<float2*>(p1) = make_float2(acc[a][b][2], acc[a][b][3]);
        }
    }
}

// ---------------------------------------------------------------------------
extern "C" void kernel_launch(void* const* d_in, const int* in_sizes, int n_in,
                              void* d_out, int out_size) {
    const float* x  = (const float*)d_in[0];   // (4,2048,1024)
    const float* sw = (const float*)d_in[1];   // (1024,1024,12)
    const float* bw = (const float*)d_in[2];   // (1024,1024)
    float* out = (float*)d_out;                // (4,2048,1024)

    cudaFuncSetAttribute(kan_gemm, cudaFuncAttributeMaxDynamicSharedMemorySize, SMEMSZ);

    build_W<<<(OUTF_ * KD / 8) / 256, 256>>>(sw, bw);
    build_A<<<(MTOT * KD / 8) / 256, 256>>>(x);
    dim3 grid(MTOT / BM, OUTF_ / BN);
    kan_gemm<<<grid, 256, SMEMSZ>>>(out);
}

// round 4
// speedup vs baseline: 1.0751x; 1.0751x over previous
#include <cuda_runtime.h>
#include <cuda_fp16.h>
#include <cstdint>
#include <cstddef>

// ============================================================================
// KAN layer as one fp16 GEMM (portable sm_100 path: cp.async + ldmatrix +
// mma.sync.m16n8k16; plain sm_100 target rejects tcgen05):
//   out[m,o] = sum_i x[m,i]*Wb[o,i] + sum_j hat_j(clamp(x))*T_j[o,i]
// A: (8192 x 7168) fp16 row-major, 7 cols per input (x, hat0..hat5)
// W: (1024 x 7168) fp16 row-major, (Wb, T0..T5); the 12-knot tent basis
// collapses to 6 distinct knots: T0=S0+..+S3, T1..4=S4..7, T5=S8+..+S11.
// GEMM: C = A @ W^T, fp32 accum in registers.
// R4: grid order swapped for A L2-reuse, CTA tile 128x256 with 64x64 warp
// tiles (LDSM intensity 21 -> 32 FLOP/B), coalesced smem-staged prologues.
// ============================================================================

#define INF_   1024
#define OUTF_  1024
#define MTOT   8192
#define KD     7168            // 7 * 1024
#define BM     128
#define BN     256
#define BK     64
#define KT     (KD / BK)       // 112
#define STG    3
#define ASZ    (BM * BK * 2)   // 16384
#define BSZ    (BN * BK * 2)   // 32768
#define STAGEB (ASZ + BSZ)     // 49152
#define SMEMSZ (STG * STAGEB)  // 147456

__device__ __align__(16) __half g_A[(size_t)MTOT * KD];   // 112 MB
__device__ __align__(16) __half g_W[(size_t)OUTF_ * KD];  // 14 MB

// ---------------------------------------------------------------------------
// helpers
// ---------------------------------------------------------------------------
__device__ __forceinline__ uint32_t s2u(const void* p) {
    uint32_t a;
    asm("{ .reg .u64 t; cvta.to.shared.u64 t, %1; cvt.u32.u64 %0, t; }"
        : "=r"(a) : "l"(p));
    return a;
}
__device__ __forceinline__ void cpasync16(uint32_t dst, const void* src) {
    asm volatile("cp.async.cg.shared.global [%0], [%1], 16;" :: "r"(dst), "l"(src));
}
__device__ __forceinline__ void ldsm4(uint32_t* r, uint32_t a) {
    asm volatile("ldmatrix.sync.aligned.m8n8.x4.shared.b16 {%0,%1,%2,%3}, [%4];"
                 : "=r"(r[0]), "=r"(r[1]), "=r"(r[2]), "=r"(r[3]) : "r"(a));
}
__device__ __forceinline__ void mma16816(float* c, const uint32_t* a, const uint32_t* b) {
    asm volatile(
        "mma.sync.aligned.m16n8k16.row.col.f32.f16.f16.f32 "
        "{%0,%1,%2,%3}, {%4,%5,%6,%7}, {%8,%9}, {%0,%1,%2,%3};"
        : "+f"(c[0]), "+f"(c[1]), "+f"(c[2]), "+f"(c[3])
        : "r"(a[0]), "r"(a[1]), "r"(a[2]), "r"(a[3]), "r"(b[0]), "r"(b[1]));
}

// ---------------------------------------------------------------------------
// Prologue 1: build A fp16 row-major from x. One thread per (m,i) pair.
// Pair p -> output halves [p*7, p*7+7): [x, hat0..hat5]. Output offsets are
// contiguous across p, so a 256-thread block emits 1792 halves = 3584B which
// we stage in smem and flush as 224 uint4 (fully coalesced).
// ---------------------------------------------------------------------------
__global__ void __launch_bounds__(256) build_A(const float* __restrict__ x) {
    __shared__ __half st[256 * 7];
    int tid = threadIdx.x;
    size_t p = (size_t)blockIdx.x * 256 + tid;
    float xv = x[p];
    float xc = fminf(fmaxf(xv, -1.0f), 1.0f);
    st[tid * 7] = __float2half_rn(xv);
    #pragma unroll
    for (int c = 0; c < 6; c++) {
        float knot = 0.4f * (float)c - 1.0f;
        float h = fmaxf(0.0f, 1.0f - fabsf(xc - knot) * 2.5f);
        st[tid * 7 + 1 + c] = __float2half_rn(h);
    }
    __syncthreads();
    uint4* dst = reinterpret_cast<uint4*>(
        reinterpret_cast<char*>(g_A) + (size_t)blockIdx.x * 3584);
    const uint4* src = reinterpret_cast<const uint4*>(st);
    if (tid < 224) dst[tid] = src[tid];
}

// ---------------------------------------------------------------------------
// Prologue 2: build W fp16 row-major. One thread per (o,i) pair.
// Reads 12 floats (3 aligned float4, coalesced across threads), emits
// [bw, T0..T5] with T0=S0+S1+S2+S3, T1..4=S4..7, T5=S8+S9+S10+S11.
// ---------------------------------------------------------------------------
__global__ void __launch_bounds__(256) build_W(const float* __restrict__ sw,
                                               const float* __restrict__ bw) {
    __shared__ __half st[256 * 7];
    int tid = threadIdx.x;
    size_t p = (size_t)blockIdx.x * 256 + tid;
    const float4* s4 = reinterpret_cast<const float4*>(sw + p * 12);
    float4 a = s4[0], b = s4[1], c = s4[2];
    st[tid * 7 + 0] = __float2half_rn(bw[p]);
    st[tid * 7 + 1] = __float2half_rn(a.x + a.y + a.z + a.w);  // T0
    st[tid * 7 + 2] = __float2half_rn(b.x);                     // T1 = S4
    st[tid * 7 + 3] = __float2half_rn(b.y);                     // T2 = S5
    st[tid * 7 + 4] = __float2half_rn(b.z);                     // T3 = S6
    st[tid * 7 + 5] = __float2half_rn(b.w);                     // T4 = S7
    st[tid * 7 + 6] = __float2half_rn(c.x + c.y + c.z + c.w);  // T5
    __syncthreads();
    uint4* dst = reinterpret_cast<uint4*>(
        reinterpret_cast<char*>(g_W) + (size_t)blockIdx.x * 3584);
    const uint4* src = reinterpret_cast<const uint4*>(st);
    if (tid < 224) dst[tid] = src[tid];
}

// ---------------------------------------------------------------------------
// GEMM: out = A(8192x7168) @ W(1024x7168)^T, fp16 in, fp32 reg accum.
// CTA 128x256x64, 3-stage cp.async pipeline, XOR-swizzled SMEM, 8 warps as
// 2M x 4N with 64x64 warp tiles (4 m16 x 8 n8), mma.m16n8k16.
// blockIdx.x = N tile (fast) so concurrent CTAs share the A tile in L2.
// ---------------------------------------------------------------------------
__global__ void __launch_bounds__(256, 1) kan_gemm(float* __restrict__ out) {
    extern __shared__ unsigned char smem[];
    uint32_t sb = s2u(smem);
    int tid = threadIdx.x;
    int wid = tid >> 5, lid = tid & 31;
    int n0 = blockIdx.x * BN;
    int m0 = blockIdx.y * BM;

    const char* aG = reinterpret_cast<const char*>(g_A) + (size_t)m0 * (KD * 2);
    const char* bG = reinterpret_cast<const char*>(g_W) + (size_t)n0 * (KD * 2);

    #define LOAD_STAGE(s, it)                                                          \
        do {                                                                           \
            uint32_t base_ = sb + (s) * STAGEB;                                        \
            const char* ga_ = aG + (size_t)(it) * 128;                                 \
            const char* gb_ = bG + (size_t)(it) * 128;                                 \
            _Pragma("unroll")                                                          \
            for (int j = 0; j < 4; j++) {   /* A: 1024 chunks */                       \
                int id_ = tid + j * 256;                                               \
                int r_ = id_ >> 3, c_ = id_ & 7;                                       \
                cpasync16(base_ + r_ * 128 + ((c_ ^ (r_ & 7)) << 4),                   \
                          ga_ + (size_t)r_ * (KD * 2) + c_ * 16);                      \
            }                                                                          \
            _Pragma("unroll")                                                          \
            for (int j = 0; j < 8; j++) {   /* B: 2048 chunks */                       \
                int id_ = tid + j * 256;                                               \
                int r_ = id_ >> 3, c_ = id_ & 7;                                       \
                cpasync16(base_ + ASZ + r_ * 128 + ((c_ ^ (r_ & 7)) << 4),             \
                          gb_ + (size_t)r_ * (KD * 2) + c_ * 16);                      \
            }                                                                          \
            asm volatile("cp.async.commit_group;");                                    \
        } while (0)

    int wm = (wid >> 2) * 64;   // 2 M warp-groups
    int wn = (wid & 3) * 64;    // 4 N warp-groups

    float acc[4][8][4] = {};

    LOAD_STAGE(0, 0);
    LOAD_STAGE(1, 1);

    int mi = lid >> 3;            // matrix index within ldsm x4
    int lr = lid & 7;             // row within 8x8 matrix

    for (int it = 0; it < KT; ++it) {
        if (it + 1 < KT) asm volatile("cp.async.wait_group 1;");
        else             asm volatile("cp.async.wait_group 0;");
        __syncthreads();
        if (it + 2 < KT) LOAD_STAGE((it + 2) % STG, it + 2);

        uint32_t asB = sb + (it % STG) * STAGEB;
        uint32_t bsB = asB + ASZ;

        #pragma unroll
        for (int ks = 0; ks < 4; ++ks) {
            uint32_t aF[4][4], bF[4][4];
            #pragma unroll
            for (int a = 0; a < 4; a++) {
                int mr = wm + a * 16 + lr + (mi & 1) * 8;
                int kc = ks * 2 + (mi >> 1);            // 16B chunk index
                ldsm4(aF[a], asB + mr * 128 + ((kc ^ (mr & 7)) << 4));
            }
            #pragma unroll
            for (int q = 0; q < 4; q++) {
                int nr = wn + q * 16 + ((mi >> 1) << 3) + lr;
                int kc = ks * 2 + (mi & 1);
                ldsm4(bF[q], bsB + nr * 128 + ((kc ^ (nr & 7)) << 4));
            }
            #pragma unroll
            for (int a = 0; a < 4; a++)
                #pragma unroll
                for (int b = 0; b < 8; b++)
                    mma16816(acc[a][b], aF[a], &bF[b >> 1][(b & 1) * 2]);
        }
    }

    // epilogue: fp32 register tiles -> gmem
    int row0 = m0 + wm + (lid >> 2);
    int col0 = n0 + wn + (lid & 3) * 2;
    #pragma unroll
    for (int a = 0; a < 4; a++) {
        #pragma unroll
        for (int b = 0; b < 8; b++) {
            float* p0 = out + (size_t)(row0 + a * 16) * OUTF_ + col0 + b * 8;
            float* p1 = p0 + (size_t)8 * OUTF_;
            *reinterpret_cast<float2*>(p0) = make_float2(acc[a][b][0], acc[a][b][1]);
            *reinterpret_cast<float2*>(p1) = make_float2(acc[a][b][2], acc[a][b][3]);
        }
    }
}

// ---------------------------------------------------------------------------
extern "C" void kernel_launch(void* const* d_in, const int* in_sizes, int n_in,
                              void* d_out, int out_size) {
    const float* x  = (const float*)d_in[0];   // (4,2048,1024)
    const float* sw = (const float*)d_in[1];   // (1024,1024,12)
    const float* bw = (const float*)d_in[2];   // (1024,1024)
    float* out = (float*)d_out;                // (4,2048,1024)

    cudaFuncSetAttribute(kan_gemm, cudaFuncAttributeMaxDynamicSharedMemorySize, SMEMSZ);

    build_W<<<(OUTF_ * INF_) / 256, 256>>>(sw, bw);
    build_A<<<(MTOT * INF_) / 256, 256>>>(x);
    dim3 grid(OUTF_ / BN, MTOT / BM);   // x = N tile (fast) -> A L2 reuse
    kan_gemm<<<grid, 256, SMEMSZ>>>(out);
}

// round 5
// speedup vs baseline: 1.2598x; 1.1718x over previous
#include <cuda_runtime.h>
#include <cuda_fp16.h>
#include <cstdint>
#include <cstddef>

// ============================================================================
// KAN layer as one fp16 GEMM (portable sm_100 path: cp.async + ldmatrix +
// mma.sync.m16n8k16):
//   out[m,o] = x@bw^T + sum_j hat_j(clamp(x)) T_j  (12-knot basis -> 6 knots)
// Partition of unity: sum_j hat_j = 1  =>  spline = T0 + sum_{j>=1}(T_j-T0)hat_j
// so the T0 term becomes a per-o fp32 BIAS and K drops to 6 per input:
// A: (8192 x 6144) fp16 [x, hat1..hat5] ; W: (1024 x 6144) [bw, T1-T0..T5-T0]
// bias[o] = sum_i T0[o,i] (fp32, added in GEMM epilogue).
// T0=S0+S1+S2+S3, T1..4=S4..S7, T5=S8+S9+S10+S11.
// ============================================================================

#define INF_   1024
#define OUTF_  1024
#define MTOT   8192
#define KD     6144            // 6 * 1024
#define BM     128
#define BN     256
#define BK     64
#define KT     (KD / BK)       // 96
#define STG    4
#define ASZ    (BM * BK * 2)   // 16384
#define BSZ    (BN * BK * 2)   // 32768
#define STAGEB (ASZ + BSZ)     // 49152
#define SMEMSZ (STG * STAGEB)  // 196608

__device__ __align__(16) __half g_A[(size_t)MTOT * KD];   // 96 MB
__device__ __align__(16) __half g_W[(size_t)OUTF_ * KD];  // 12 MB
__device__ float g_biasp[4096];   // per-(o, i-block) partials of sum_i T0
__device__ float g_bias[1024];    // final bias per o

// ---------------------------------------------------------------------------
// helpers
// ---------------------------------------------------------------------------
__device__ __forceinline__ uint32_t s2u(const void* p) {
    uint32_t a;
    asm("{ .reg .u64 t; cvta.to.shared.u64 t, %1; cvt.u32.u64 %0, t; }"
        : "=r"(a) : "l"(p));
    return a;
}
__device__ __forceinline__ void cpasync16(uint32_t dst, const void* src) {
    asm volatile("cp.async.cg.shared.global [%0], [%1], 16;" :: "r"(dst), "l"(src));
}
__device__ __forceinline__ void ldsm4(uint32_t* r, uint32_t a) {
    asm volatile("ldmatrix.sync.aligned.m8n8.x4.shared.b16 {%0,%1,%2,%3}, [%4];"
                 : "=r"(r[0]), "=r"(r[1]), "=r"(r[2]), "=r"(r[3]) : "r"(a));
}
__device__ __forceinline__ void mma16816(float* c, const uint32_t* a, const uint32_t* b) {
    asm volatile(
        "mma.sync.aligned.m16n8k16.row.col.f32.f16.f16.f32 "
        "{%0,%1,%2,%3}, {%4,%5,%6,%7}, {%8,%9}, {%0,%1,%2,%3};"
        : "+f"(c[0]), "+f"(c[1]), "+f"(c[2]), "+f"(c[3])
        : "r"(a[0]), "r"(a[1]), "r"(a[2]), "r"(a[3]), "r"(b[0]), "r"(b[1]));
}

// ---------------------------------------------------------------------------
// build_A: one thread per (m,i). Emits 6 halves [x, hat1..hat5] contiguous.
// Block of 256 pairs -> 3072B staged in smem, flushed as 192 uint4.
// ---------------------------------------------------------------------------
__global__ void __launch_bounds__(256) build_A(const float* __restrict__ x) {
    __shared__ __half st[256 * 6];
    int tid = threadIdx.x;
    size_t p = (size_t)blockIdx.x * 256 + tid;
    float xv = x[p];
    float xc = fminf(fmaxf(xv, -1.0f), 1.0f);
    st[tid * 6] = __float2half_rn(xv);
    #pragma unroll
    for (int j = 1; j <= 5; j++) {
        float knot = 0.4f * (float)j - 1.0f;
        float h = fmaxf(0.0f, 1.0f - fabsf(xc - knot) * 2.5f);
        st[tid * 6 + j] = __float2half_rn(h);
    }
    __syncthreads();
    uint4* dst = reinterpret_cast<uint4*>(
        reinterpret_cast<char*>(g_A) + (size_t)blockIdx.x * 3072);
    const uint4* src = reinterpret_cast<const uint4*>(st);
    if (tid < 192) dst[tid] = src[tid];
}

// ---------------------------------------------------------------------------
// build_W: one thread per (o,i). Emits [bw, T1-T0 .. T5-T0]; block-reduces
// T0 into g_biasp[block] (each block lies within one o: 4 blocks per o).
// ---------------------------------------------------------------------------
__global__ void __launch_bounds__(256) build_W(const float* __restrict__ sw,
                                               const float* __restrict__ bw) {
    __shared__ __half st[256 * 6];
    __shared__ float red[256];
    int tid = threadIdx.x;
    size_t p = (size_t)blockIdx.x * 256 + tid;
    const float4* s4 = reinterpret_cast<const float4*>(sw + p * 12);
    float4 a = s4[0], b = s4[1], c = s4[2];
    float T0 = a.x + a.y + a.z + a.w;
    float T5 = c.x + c.y + c.z + c.w;
    st[tid * 6 + 0] = __float2half_rn(bw[p]);
    st[tid * 6 + 1] = __float2half_rn(b.x - T0);
    st[tid * 6 + 2] = __float2half_rn(b.y - T0);
    st[tid * 6 + 3] = __float2half_rn(b.z - T0);
    st[tid * 6 + 4] = __float2half_rn(b.w - T0);
    st[tid * 6 + 5] = __float2half_rn(T5 - T0);
    red[tid] = T0;
    __syncthreads();
    #pragma unroll
    for (int s = 128; s > 0; s >>= 1) {
        if (tid < s) red[tid] += red[tid + s];
        __syncthreads();
    }
    if (tid == 0) g_biasp[blockIdx.x] = red[0];
    uint4* dst = reinterpret_cast<uint4*>(
        reinterpret_cast<char*>(g_W) + (size_t)blockIdx.x * 3072);
    const uint4* src = reinterpret_cast<const uint4*>(st);
    if (tid < 192) dst[tid] = src[tid];
}

__global__ void sum_bias() {
    int o = blockIdx.x * 256 + threadIdx.x;
    g_bias[o] = g_biasp[o * 4] + g_biasp[o * 4 + 1]
              + g_biasp[o * 4 + 2] + g_biasp[o * 4 + 3];
}

// ---------------------------------------------------------------------------
// GEMM: out = A(8192x6144) @ W(1024x6144)^T + bias, fp16 in, fp32 reg accum.
// CTA 128x256x64, 4-stage cp.async pipeline (uniform commit in tail),
// XOR-swizzled SMEM, 8 warps 2Mx4N, warp tile 64x64, mma.m16n8k16.
// blockIdx.x = N tile (fast) so concurrent CTAs share the A tile in L2.
// ---------------------------------------------------------------------------
__global__ void __launch_bounds__(256, 1) kan_gemm(float* __restrict__ out) {
    extern __shared__ unsigned char smem[];
    uint32_t sb = s2u(smem);
    int tid = threadIdx.x;
    int wid = tid >> 5, lid = tid & 31;
    int n0 = blockIdx.x * BN;
    int m0 = blockIdx.y * BM;

    const char* aG = reinterpret_cast<const char*>(g_A) + (size_t)m0 * (KD * 2);
    const char* bG = reinterpret_cast<const char*>(g_W) + (size_t)n0 * (KD * 2);

    #define LOAD_STAGE(s, it)                                                          \
        do {                                                                           \
            uint32_t base_ = sb + (s) * STAGEB;                                        \
            const char* ga_ = aG + (size_t)(it) * 128;                                 \
            const char* gb_ = bG + (size_t)(it) * 128;                                 \
            _Pragma("unroll")                                                          \
            for (int j = 0; j < 4; j++) {   /* A: 1024 chunks */                       \
                int id_ = tid + j * 256;                                               \
                int r_ = id_ >> 3, c_ = id_ & 7;                                       \
                cpasync16(base_ + r_ * 128 + ((c_ ^ (r_ & 7)) << 4),                   \
                          ga_ + (size_t)r_ * (KD * 2) + c_ * 16);                      \
            }                                                                          \
            _Pragma("unroll")                                                          \
            for (int j = 0; j < 8; j++) {   /* B: 2048 chunks */                       \
                int id_ = tid + j * 256;                                               \
                int r_ = id_ >> 3, c_ = id_ & 7;                                       \
                cpasync16(base_ + ASZ + r_ * 128 + ((c_ ^ (r_ & 7)) << 4),             \
                          gb_ + (size_t)r_ * (KD * 2) + c_ * 16);                      \
            }                                                                          \
            asm volatile("cp.async.commit_group;");                                    \
        } while (0)

    int wm = (wid >> 2) * 64;   // 2 M warp-groups
    int wn = (wid & 3) * 64;    // 4 N warp-groups

    float acc[4][8][4] = {};

    LOAD_STAGE(0, 0);
    LOAD_STAGE(1, 1);
    LOAD_STAGE(2, 2);

    int mi = lid >> 3;            // matrix index within ldsm x4
    int lr = lid & 7;             // row within 8x8 matrix

    for (int it = 0; it < KT; ++it) {
        asm volatile("cp.async.wait_group 2;");
        __syncthreads();
        if (it + 3 < KT) LOAD_STAGE((it + 3) & 3, it + 3);
        else             asm volatile("cp.async.commit_group;");  // keep count uniform

        uint32_t asB = sb + (it & 3) * STAGEB;
        uint32_t bsB = asB + ASZ;

        #pragma unroll
        for (int ks = 0; ks < 4; ++ks) {
            uint32_t aF[4][4], bF[4][4];
            #pragma unroll
            for (int a = 0; a < 4; a++) {
                int mr = wm + a * 16 + lr + (mi & 1) * 8;
                int kc = ks * 2 + (mi >> 1);            // 16B chunk index
                ldsm4(aF[a], asB + mr * 128 + ((kc ^ (mr & 7)) << 4));
            }
            #pragma unroll
            for (int q = 0; q < 4; q++) {
                int nr = wn + q * 16 + ((mi >> 1) << 3) + lr;
                int kc = ks * 2 + (mi & 1);
                ldsm4(bF[q], bsB + nr * 128 + ((kc ^ (nr & 7)) << 4));
            }
            #pragma unroll
            for (int a = 0; a < 4; a++)
                #pragma unroll
                for (int b = 0; b < 8; b++)
                    mma16816(acc[a][b], aF[a], &bF[b >> 1][(b & 1) * 2]);
        }
    }

    // epilogue: add fp32 bias, store fp32 tiles
    int row0 = m0 + wm + (lid >> 2);
    int col0 = n0 + wn + (lid & 3) * 2;
    #pragma unroll
    for (int b = 0; b < 8; b++) {
        float bv0 = g_bias[col0 + b * 8];
        float bv1 = g_bias[col0 + b * 8 + 1];
        #pragma unroll
        for (int a = 0; a < 4; a++) {
            float* p0 = out + (size_t)(row0 + a * 16) * OUTF_ + col0 + b * 8;
            float* p1 = p0 + (size_t)8 * OUTF_;
            *reinterpret_cast<float2*>(p0) =
                make_float2(acc[a][b][0] + bv0, acc[a][b][1] + bv1);
            *reinterpret_cast<float2*>(p1) =
                make_float2(acc[a][b][2] + bv0, acc[a][b][3] + bv1);
        }
    }
}

// ---------------------------------------------------------------------------
extern "C" void kernel_launch(void* const* d_in, const int* in_sizes, int n_in,
                              void* d_out, int out_size) {
    const float* x  = (const float*)d_in[0];   // (4,2048,1024)
    const float* sw = (const float*)d_in[1];   // (1024,1024,12)
    const float* bw = (const float*)d_in[2];   // (1024,1024)
    float* out = (float*)d_out;                // (4,2048,1024)

    cudaFuncSetAttribute(kan_gemm, cudaFuncAttributeMaxDynamicSharedMemorySize, SMEMSZ);

    build_W<<<(OUTF_ * INF_) / 256, 256>>>(sw, bw);
    sum_bias<<<4, 256>>>();
    build_A<<<(MTOT * INF_) / 256, 256>>>(x);
    dim3 grid(OUTF_ / BN, MTOT / BM);   // x = N tile (fast) -> A L2 reuse
    kan_gemm<<<grid, 256, SMEMSZ>>>(out);
}

// round 6
// speedup vs baseline: 1.3195x; 1.0474x over previous
#include <cuda_runtime.h>
#include <cuda_fp16.h>
#include <cstdint>
#include <cstddef>

// ============================================================================
// KAN layer as one fp16 GEMM (portable sm_100 path: cp.async + ldmatrix +
// mma.sync.m16n8k16):
//   out[m,o] = x@bw^T + sum_j hat_j(clamp(x)) T_j  (12-knot basis -> 6 knots)
// Partition of unity: sum_j hat_j = 1  =>  spline = T0 + sum_{j>=1}(T_j-T0)hat_j
// so the T0 term becomes a per-o fp32 BIAS and K drops to 6 per input:
// A: (8192 x 6144) fp16 [x, hat1..hat5] ; W: (1024 x 6144) [bw, T1-T0..T5-T0]
// bias[o] = sum_i T0[o,i] (fp32, added in GEMM epilogue).
// R6: CTA 128x128, warp tile 64x32, <=128 regs -> 2 CTAs/SM (16 warps/SM,
// 4/SMSP) to close the 38% tensor-pipe idle seen at occ=12.5%.
// ============================================================================

#define INF_   1024
#define OUTF_  1024
#define MTOT   8192
#define KD     6144            // 6 * 1024
#define BM     128
#define BN     128
#define BK     64
#define KT     (KD / BK)       // 96
#define STG    3
#define ASZ    (BM * BK * 2)   // 16384
#define BSZ    (BN * BK * 2)   // 16384
#define STAGEB (ASZ + BSZ)     // 32768
#define SMEMSZ (STG * STAGEB)  // 98304

__device__ __align__(16) __half g_A[(size_t)MTOT * KD];   // 96 MB
__device__ __align__(16) __half g_W[(size_t)OUTF_ * KD];  // 12 MB
__device__ float g_biasp[4096];   // per-(o, i-block) partials of sum_i T0
__device__ float g_bias[1024];    // final bias per o

// ---------------------------------------------------------------------------
// helpers
// ---------------------------------------------------------------------------
__device__ __forceinline__ uint32_t s2u(const void* p) {
    uint32_t a;
    asm("{ .reg .u64 t; cvta.to.shared.u64 t, %1; cvt.u32.u64 %0, t; }"
        : "=r"(a) : "l"(p));
    return a;
}
__device__ __forceinline__ void cpasync16(uint32_t dst, const void* src) {
    asm volatile("cp.async.cg.shared.global [%0], [%1], 16;" :: "r"(dst), "l"(src));
}
__device__ __forceinline__ void ldsm4(uint32_t* r, uint32_t a) {
    asm volatile("ldmatrix.sync.aligned.m8n8.x4.shared.b16 {%0,%1,%2,%3}, [%4];"
                 : "=r"(r[0]), "=r"(r[1]), "=r"(r[2]), "=r"(r[3]) : "r"(a));
}
__device__ __forceinline__ void mma16816(float* c, const uint32_t* a, const uint32_t* b) {
    asm volatile(
        "mma.sync.aligned.m16n8k16.row.col.f32.f16.f16.f32 "
        "{%0,%1,%2,%3}, {%4,%5,%6,%7}, {%8,%9}, {%0,%1,%2,%3};"
        : "+f"(c[0]), "+f"(c[1]), "+f"(c[2]), "+f"(c[3])
        : "r"(a[0]), "r"(a[1]), "r"(a[2]), "r"(a[3]), "r"(b[0]), "r"(b[1]));
}

// ---------------------------------------------------------------------------
// build_A: one thread per (m,i). Emits 6 halves [x, hat1..hat5] contiguous.
// Block of 256 pairs -> 3072B staged in smem, flushed as 192 uint4.
// ---------------------------------------------------------------------------
__global__ void __launch_bounds__(256) build_A(const float* __restrict__ x) {
    __shared__ __half st[256 * 6];
    int tid = threadIdx.x;
    size_t p = (size_t)blockIdx.x * 256 + tid;
    float xv = x[p];
    float xc = fminf(fmaxf(xv, -1.0f), 1.0f);
    st[tid * 6] = __float2half_rn(xv);
    #pragma unroll
    for (int j = 1; j <= 5; j++) {
        float knot = 0.4f * (float)j - 1.0f;
        float h = fmaxf(0.0f, 1.0f - fabsf(xc - knot) * 2.5f);
        st[tid * 6 + j] = __float2half_rn(h);
    }
    __syncthreads();
    uint4* dst = reinterpret_cast<uint4*>(
        reinterpret_cast<char*>(g_A) + (size_t)blockIdx.x * 3072);
    const uint4* src = reinterpret_cast<const uint4*>(st);
    if (tid < 192) dst[tid] = src[tid];
}

// ---------------------------------------------------------------------------
// build_W: one thread per (o,i). Emits [bw, T1-T0 .. T5-T0]; block-reduces
// T0 into g_biasp[block] (each block lies within one o: 4 blocks per o).
// ---------------------------------------------------------------------------
__global__ void __launch_bounds__(256) build_W(const float* __restrict__ sw,
                                               const float* __restrict__ bw) {
    __shared__ __half st[256 * 6];
    __shared__ float red[256];
    int tid = threadIdx.x;
    size_t p = (size_t)blockIdx.x * 256 + tid;
    const float4* s4 = reinterpret_cast<const float4*>(sw + p * 12);
    float4 a = s4[0], b = s4[1], c = s4[2];
    float T0 = a.x + a.y + a.z + a.w;
    float T5 = c.x + c.y + c.z + c.w;
    st[tid * 6 + 0] = __float2half_rn(bw[p]);
    st[tid * 6 + 1] = __float2half_rn(b.x - T0);
    st[tid * 6 + 2] = __float2half_rn(b.y - T0);
    st[tid * 6 + 3] = __float2half_rn(b.z - T0);
    st[tid * 6 + 4] = __float2half_rn(b.w - T0);
    st[tid * 6 + 5] = __float2half_rn(T5 - T0);
    red[tid] = T0;
    __syncthreads();
    #pragma unroll
    for (int s = 128; s > 0; s >>= 1) {
        if (tid < s) red[tid] += red[tid + s];
        __syncthreads();
    }
    if (tid == 0) g_biasp[blockIdx.x] = red[0];
    uint4* dst = reinterpret_cast<uint4*>(
        reinterpret_cast<char*>(g_W) + (size_t)blockIdx.x * 3072);
    const uint4* src = reinterpret_cast<const uint4*>(st);
    if (tid < 192) dst[tid] = src[tid];
}

__global__ void sum_bias() {
    int o = blockIdx.x * 256 + threadIdx.x;
    g_bias[o] = g_biasp[o * 4] + g_biasp[o * 4 + 1]
              + g_biasp[o * 4 + 2] + g_biasp[o * 4 + 3];
}

// ---------------------------------------------------------------------------
// GEMM: out = A(8192x6144) @ W(1024x6144)^T + bias, fp16 in, fp32 reg accum.
// CTA 128x128x64, 3-stage cp.async ring, XOR-swizzled SMEM, 8 warps 2Mx4N,
// warp tile 64x32 (4 m16 x 4 n8), mma.m16n8k16, 2 CTAs/SM.
// blockIdx.x = N tile (fast) so concurrent CTAs share the A tile in L2.
// ---------------------------------------------------------------------------
__global__ void __launch_bounds__(256, 2) kan_gemm(float* __restrict__ out) {
    extern __shared__ unsigned char smem[];
    uint32_t sb = s2u(smem);
    int tid = threadIdx.x;
    int wid = tid >> 5, lid = tid & 31;
    int n0 = blockIdx.x * BN;
    int m0 = blockIdx.y * BM;

    const char* aG = reinterpret_cast<const char*>(g_A) + (size_t)m0 * (KD * 2);
    const char* bG = reinterpret_cast<const char*>(g_W) + (size_t)n0 * (KD * 2);

    #define LOAD_STAGE(s, it)                                                          \
        do {                                                                           \
            uint32_t base_ = sb + (s) * STAGEB;                                        \
            const char* ga_ = aG + (size_t)(it) * 128;                                 \
            const char* gb_ = bG + (size_t)(it) * 128;                                 \
            _Pragma("unroll")                                                          \
            for (int j = 0; j < 4; j++) {   /* A: 1024 chunks */                       \
                int id_ = tid + j * 256;                                               \
                int r_ = id_ >> 3, c_ = id_ & 7;                                       \
                cpasync16(base_ + r_ * 128 + ((c_ ^ (r_ & 7)) << 4),                   \
                          ga_ + (size_t)r_ * (KD * 2) + c_ * 16);                      \
            }                                                                          \
            _Pragma("unroll")                                                          \
            for (int j = 0; j < 4; j++) {   /* B: 1024 chunks */                       \
                int id_ = tid + j * 256;                                               \
                int r_ = id_ >> 3, c_ = id_ & 7;                                       \
                cpasync16(base_ + ASZ + r_ * 128 + ((c_ ^ (r_ & 7)) << 4),             \
                          gb_ + (size_t)r_ * (KD * 2) + c_ * 16);                      \
            }                                                                          \
            asm volatile("cp.async.commit_group;");                                    \
        } while (0)

    int wm = (wid >> 2) * 64;   // 2 M warp-groups
    int wn = (wid & 3) * 32;    // 4 N warp-groups

    float acc[4][4][4] = {};

    LOAD_STAGE(0, 0);
    LOAD_STAGE(1, 1);

    int mi = lid >> 3;            // matrix index within ldsm x4
    int lr = lid & 7;             // row within 8x8 matrix

    int cur = 0, nxt = 2;
    for (int it = 0; it < KT; ++it) {
        asm volatile("cp.async.wait_group 1;");
        __syncthreads();
        if (it + 2 < KT) LOAD_STAGE(nxt, it + 2);
        else             asm volatile("cp.async.commit_group;");  // uniform count

        uint32_t asB = sb + cur * STAGEB;
        uint32_t bsB = asB + ASZ;

        #pragma unroll
        for (int ks = 0; ks < 4; ++ks) {
            uint32_t aF[4][4], bF[2][4];
            #pragma unroll
            for (int a = 0; a < 4; a++) {
                int mr = wm + a * 16 + lr + (mi & 1) * 8;
                int kc = ks * 2 + (mi >> 1);            // 16B chunk index
                ldsm4(aF[a], asB + mr * 128 + ((kc ^ (mr & 7)) << 4));
            }
            #pragma unroll
            for (int q = 0; q < 2; q++) {
                int nr = wn + q * 16 + ((mi >> 1) << 3) + lr;
                int kc = ks * 2 + (mi & 1);
                ldsm4(bF[q], bsB + nr * 128 + ((kc ^ (nr & 7)) << 4));
            }
            #pragma unroll
            for (int a = 0; a < 4; a++)
                #pragma unroll
                for (int b = 0; b < 4; b++)
                    mma16816(acc[a][b], aF[a], &bF[b >> 1][(b & 1) * 2]);
        }
        __syncthreads();   // protect stage about to be overwritten
        cur = (cur == STG - 1) ? 0 : cur + 1;
        nxt = (nxt == STG - 1) ? 0 : nxt + 1;
    }

    // epilogue: add fp32 bias, store fp32 tiles
    int row0 = m0 + wm + (lid >> 2);
    int col0 = n0 + wn + (lid & 3) * 2;
    #pragma unroll
    for (int b = 0; b < 4; b++) {
        float bv0 = g_bias[col0 + b * 8];
        float bv1 = g_bias[col0 + b * 8 + 1];
        #pragma unroll
        for (int a = 0; a < 4; a++) {
            float* p0 = out + (size_t)(row0 + a * 16) * OUTF_ + col0 + b * 8;
            float* p1 = p0 + (size_t)8 * OUTF_;
            *reinterpret_cast<float2*>(p0) =
                make_float2(acc[a][b][0] + bv0, acc[a][b][1] + bv1);
            *reinterpret_cast<float2*>(p1) =
                make_float2(acc[a][b][2] + bv0, acc[a][b][3] + bv1);
        }
    }
}

// ---------------------------------------------------------------------------
extern "C" void kernel_launch(void* const* d_in, const int* in_sizes, int n_in,
                              void* d_out, int out_size) {
    const float* x  = (const float*)d_in[0];   // (4,2048,1024)
    const float* sw = (const float*)d_in[1];   // (1024,1024,12)
    const float* bw = (const float*)d_in[2];   // (1024,1024)
    float* out = (float*)d_out;                // (4,2048,1024)

    cudaFuncSetAttribute(kan_gemm, cudaFuncAttributeMaxDynamicSharedMemorySize, SMEMSZ);

    build_W<<<(OUTF_ * INF_) / 256, 256>>>(sw, bw);
    sum_bias<<<4, 256>>>();
    build_A<<<(MTOT * INF_) / 256, 256>>>(x);
    dim3 grid(OUTF_ / BN, MTOT / BM);   // x = N tile (fast) -> A L2 reuse
    kan_gemm<<<grid, 256, SMEMSZ>>>(out);
}

// round 7
// speedup vs baseline: 1.3336x; 1.0107x over previous
#include <cuda_runtime.h>
#include <cuda_fp16.h>
#include <cstdint>
#include <cstddef>

// ============================================================================
// KAN layer as one fp16 GEMM (portable sm_100 path: cp.async + ldmatrix +
// mma.sync.m16n8k16):
//   out[m,o] = x@bw^T + sum_j hat_j(clamp(x)) T_j  (12-knot basis -> 6 knots)
// Partition of unity: sum_j hat_j = 1  =>  spline = T0 + sum_{j>=1}(T_j-T0)hat_j
// T0 term -> per-o fp32 bias; K = 6 per input:
// A: (8192 x 6144) fp16 [x, hat1..hat5] ; W: (1024 x 6144) [bw, T1-T0..T5-T0]
// R7: k16-level fragment double-buffering (ldsm for ks+1 issued before MMAs
// of ks -> no smem scoreboard stall on the critical path) + single barrier
// per K-iteration. CTA 128x128, warp tile 64x32, 2 CTAs/SM.
// ============================================================================

#define INF_   1024
#define OUTF_  1024
#define MTOT   8192
#define KD     6144            // 6 * 1024
#define BM     128
#define BN     128
#define BK     64
#define KT     (KD / BK)       // 96
#define STG    3
#define ASZ    (BM * BK * 2)   // 16384
#define BSZ    (BN * BK * 2)   // 16384
#define STAGEB (ASZ + BSZ)     // 32768
#define SMEMSZ (STG * STAGEB)  // 98304

__device__ __align__(16) __half g_A[(size_t)MTOT * KD];   // 96 MB
__device__ __align__(16) __half g_W[(size_t)OUTF_ * KD];  // 12 MB
__device__ float g_biasp[4096];   // per-(o, i-block) partials of sum_i T0
__device__ float g_bias[1024];    // final bias per o

// ---------------------------------------------------------------------------
// helpers
// ---------------------------------------------------------------------------
__device__ __forceinline__ uint32_t s2u(const void* p) {
    uint32_t a;
    asm("{ .reg .u64 t; cvta.to.shared.u64 t, %1; cvt.u32.u64 %0, t; }"
        : "=r"(a) : "l"(p));
    return a;
}
__device__ __forceinline__ void cpasync16(uint32_t dst, const void* src) {
    asm volatile("cp.async.cg.shared.global [%0], [%1], 16;" :: "r"(dst), "l"(src));
}
__device__ __forceinline__ void ldsm4(uint32_t* r, uint32_t a) {
    asm volatile("ldmatrix.sync.aligned.m8n8.x4.shared.b16 {%0,%1,%2,%3}, [%4];"
                 : "=r"(r[0]), "=r"(r[1]), "=r"(r[2]), "=r"(r[3]) : "r"(a));
}
__device__ __forceinline__ void mma16816(float* c, const uint32_t* a, const uint32_t* b) {
    asm volatile(
        "mma.sync.aligned.m16n8k16.row.col.f32.f16.f16.f32 "
        "{%0,%1,%2,%3}, {%4,%5,%6,%7}, {%8,%9}, {%0,%1,%2,%3};"
        : "+f"(c[0]), "+f"(c[1]), "+f"(c[2]), "+f"(c[3])
        : "r"(a[0]), "r"(a[1]), "r"(a[2]), "r"(a[3]), "r"(b[0]), "r"(b[1]));
}

// ---------------------------------------------------------------------------
// build_A: one thread per (m,i). Emits 6 halves [x, hat1..hat5] contiguous.
// Block of 256 pairs -> 3072B staged in smem, flushed as 192 uint4.
// ---------------------------------------------------------------------------
__global__ void __launch_bounds__(256) build_A(const float* __restrict__ x) {
    __shared__ __half st[256 * 6];
    int tid = threadIdx.x;
    size_t p = (size_t)blockIdx.x * 256 + tid;
    float xv = x[p];
    float xc = fminf(fmaxf(xv, -1.0f), 1.0f);
    st[tid * 6] = __float2half_rn(xv);
    #pragma unroll
    for (int j = 1; j <= 5; j++) {
        float knot = 0.4f * (float)j - 1.0f;
        float h = fmaxf(0.0f, 1.0f - fabsf(xc - knot) * 2.5f);
        st[tid * 6 + j] = __float2half_rn(h);
    }
    __syncthreads();
    uint4* dst = reinterpret_cast<uint4*>(
        reinterpret_cast<char*>(g_A) + (size_t)blockIdx.x * 3072);
    const uint4* src = reinterpret_cast<const uint4*>(st);
    if (tid < 192) dst[tid] = src[tid];
}

// ---------------------------------------------------------------------------
// build_W: one thread per (o,i). Emits [bw, T1-T0 .. T5-T0]; block-reduces
// T0 into g_biasp[block] (each block lies within one o: 4 blocks per o).
// ---------------------------------------------------------------------------
__global__ void __launch_bounds__(256) build_W(const float* __restrict__ sw,
                                               const float* __restrict__ bw) {
    __shared__ __half st[256 * 6];
    __shared__ float red[256];
    int tid = threadIdx.x;
    size_t p = (size_t)blockIdx.x * 256 + tid;
    const float4* s4 = reinterpret_cast<const float4*>(sw + p * 12);
    float4 a = s4[0], b = s4[1], c = s4[2];
    float T0 = a.x + a.y + a.z + a.w;
    float T5 = c.x + c.y + c.z + c.w;
    st[tid * 6 + 0] = __float2half_rn(bw[p]);
    st[tid * 6 + 1] = __float2half_rn(b.x - T0);
    st[tid * 6 + 2] = __float2half_rn(b.y - T0);
    st[tid * 6 + 3] = __float2half_rn(b.z - T0);
    st[tid * 6 + 4] = __float2half_rn(b.w - T0);
    st[tid * 6 + 5] = __float2half_rn(T5 - T0);
    red[tid] = T0;
    __syncthreads();
    #pragma unroll
    for (int s = 128; s > 0; s >>= 1) {
        if (tid < s) red[tid] += red[tid + s];
        __syncthreads();
    }
    if (tid == 0) g_biasp[blockIdx.x] = red[0];
    uint4* dst = reinterpret_cast<uint4*>(
        reinterpret_cast<char*>(g_W) + (size_t)blockIdx.x * 3072);
    const uint4* src = reinterpret_cast<const uint4*>(st);
    if (tid < 192) dst[tid] = src[tid];
}

__global__ void sum_bias() {
    int o = blockIdx.x * 256 + threadIdx.x;
    g_bias[o] = g_biasp[o * 4] + g_biasp[o * 4 + 1]
              + g_biasp[o * 4 + 2] + g_biasp[o * 4 + 3];
}

// ---------------------------------------------------------------------------
// GEMM: out = A(8192x6144) @ W(1024x6144)^T + bias, fp16 in, fp32 reg accum.
// CTA 128x128x64, 3-stage cp.async ring, XOR-swizzled SMEM, 8 warps 2Mx4N,
// warp tile 64x32, mma.m16n8k16, 2 CTAs/SM, k16 fragment double-buffering.
// blockIdx.x = N tile (fast) so concurrent CTAs share the A tile in L2.
// ---------------------------------------------------------------------------
__global__ void __launch_bounds__(256, 2) kan_gemm(float* __restrict__ out) {
    extern __shared__ unsigned char smem[];
    uint32_t sb = s2u(smem);
    int tid = threadIdx.x;
    int wid = tid >> 5, lid = tid & 31;
    int n0 = blockIdx.x * BN;
    int m0 = blockIdx.y * BM;

    const char* aG = reinterpret_cast<const char*>(g_A) + (size_t)m0 * (KD * 2);
    const char* bG = reinterpret_cast<const char*>(g_W) + (size_t)n0 * (KD * 2);

    #define LOAD_STAGE(s, it)                                                          \
        do {                                                                           \
            uint32_t base_ = sb + (s) * STAGEB;                                        \
            const char* ga_ = aG + (size_t)(it) * 128;                                 \
            const char* gb_ = bG + (size_t)(it) * 128;                                 \
            _Pragma("unroll")                                                          \
            for (int j = 0; j < 4; j++) {   /* A: 1024 chunks */                       \
                int id_ = tid + j * 256;                                               \
                int r_ = id_ >> 3, c_ = id_ & 7;                                       \
                cpasync16(base_ + r_ * 128 + ((c_ ^ (r_ & 7)) << 4),                   \
                          ga_ + (size_t)r_ * (KD * 2) + c_ * 16);                      \
            }                                                                          \
            _Pragma("unroll")                                                          \
            for (int j = 0; j < 4; j++) {   /* B: 1024 chunks */                       \
                int id_ = tid + j * 256;                                               \
                int r_ = id_ >> 3, c_ = id_ & 7;                                       \
                cpasync16(base_ + ASZ + r_ * 128 + ((c_ ^ (r_ & 7)) << 4),             \
                          gb_ + (size_t)r_ * (KD * 2) + c_ * 16);                      \
            }                                                                          \
            asm volatile("cp.async.commit_group;");                                    \
        } while (0)

    int wm = (wid >> 2) * 64;   // 2 M warp-groups
    int wn = (wid & 3) * 32;    // 4 N warp-groups

    int mi = lid >> 3;            // matrix index within ldsm x4
    int lr = lid & 7;             // row within 8x8 matrix

    // fragment load for one k16 step into buffer `buf`
    uint32_t aF[2][4][4], bF[2][2][4];
    #define LDFRAGS(buf, asB_, bsB_, ks_)                                              \
        do {                                                                           \
            _Pragma("unroll")                                                          \
            for (int a_ = 0; a_ < 4; a_++) {                                           \
                int mr_ = wm + a_ * 16 + lr + (mi & 1) * 8;                            \
                int kc_ = (ks_) * 2 + (mi >> 1);                                       \
                ldsm4(aF[buf][a_], (asB_) + mr_ * 128 + ((kc_ ^ (mr_ & 7)) << 4));     \
            }                                                                          \
            _Pragma("unroll")                                                          \
            for (int q_ = 0; q_ < 2; q_++) {                                           \
                int nr_ = wn + q_ * 16 + ((mi >> 1) << 3) + lr;                        \
                int kc_ = (ks_) * 2 + (mi & 1);                                        \
                ldsm4(bF[buf][q_], (bsB_) + nr_ * 128 + ((kc_ ^ (nr_ & 7)) << 4));     \
            }                                                                          \
        } while (0)

    float acc[4][4][4] = {};

    LOAD_STAGE(0, 0);
    LOAD_STAGE(1, 1);

    int cur = 0, nxt = 2;
    for (int it = 0; it < KT; ++it) {
        asm volatile("cp.async.wait_group 1;");
        __syncthreads();
        if (it + 2 < KT) LOAD_STAGE(nxt, it + 2);
        else             asm volatile("cp.async.commit_group;");  // uniform count

        uint32_t asB = sb + cur * STAGEB;
        uint32_t bsB = asB + ASZ;

        LDFRAGS(0, asB, bsB, 0);
        #pragma unroll
        for (int ks = 0; ks < 4; ++ks) {
            if (ks < 3) LDFRAGS((ks + 1) & 1, asB, bsB, ks + 1);
            int bu = ks & 1;
            #pragma unroll
            for (int a = 0; a < 4; a++)
                #pragma unroll
                for (int b = 0; b < 4; b++)
                    mma16816(acc[a][b], aF[bu][a], &bF[bu][b >> 1][(b & 1) * 2]);
        }
        cur = (cur == STG - 1) ? 0 : cur + 1;
        nxt = (nxt == STG - 1) ? 0 : nxt + 1;
    }

    // epilogue: add fp32 bias, store fp32 tiles
    int row0 = m0 + wm + (lid >> 2);
    int col0 = n0 + wn + (lid & 3) * 2;
    #pragma unroll
    for (int b = 0; b < 4; b++) {
        float bv0 = g_bias[col0 + b * 8];
        float bv1 = g_bias[col0 + b * 8 + 1];
        #pragma unroll
        for (int a = 0; a < 4; a++) {
            float* p0 = out + (size_t)(row0 + a * 16) * OUTF_ + col0 + b * 8;
            float* p1 = p0 + (size_t)8 * OUTF_;
            *reinterpret_cast<float2*>(p0) =
                make_float2(acc[a][b][0] + bv0, acc[a][b][1] + bv1);
            *reinterpret_cast<float2*>(p1) =
                make_float2(acc[a][b][2] + bv0, acc[a][b][3] + bv1);
        }
    }
}

// ---------------------------------------------------------------------------
extern "C" void kernel_launch(void* const* d_in, const int* in_sizes, int n_in,
                              void* d_out, int out_size) {
    const float* x  = (const float*)d_in[0];   // (4,2048,1024)
    const float* sw = (const float*)d_in[1];   // (1024,1024,12)
    const float* bw = (const float*)d_in[2];   // (1024,1024)
    float* out = (float*)d_out;                // (4,2048,1024)

    cudaFuncSetAttribute(kan_gemm, cudaFuncAttributeMaxDynamicSharedMemorySize, SMEMSZ);

    build_W<<<(OUTF_ * INF_) / 256, 256>>>(sw, bw);
    sum_bias<<<4, 256>>>();
    build_A<<<(MTOT * INF_) / 256, 256>>>(x);
    dim3 grid(OUTF_ / BN, MTOT / BM);   // x = N tile (fast) -> A L2 reuse
    kan_gemm<<<grid, 256, SMEMSZ>>>(out);
}

// round 9
// speedup vs baseline: 1.3831x; 1.0371x over previous
#include <cuda_runtime.h>
#include <cuda.h>
#include <cuda_fp16.h>
#include <cstdint>
#include <cstddef>

// ============================================================================
// KAN layer as one fp16 GEMM (portable sm_100 path):
//   out[m,o] = x@bw^T + sum_j hat_j(clamp(x)) T_j  (12-knot basis -> 6 knots)
// Partition of unity: sum_j hat_j = 1 => spline = T0 + sum_{j>=1}(T_j-T0)hat_j
// T0 term -> per-o fp32 bias; K = 6 per input:
// A: (8192 x 6144) fp16 [x, hat1..hat5] ; W: (1024 x 6144) [bw, T1-T0..T5-T0]
// R9: TMA (shared::cta form) tile loads to kill the 4096 LDGSTS/SM/K-iter
// LSU+issue pressure, with the proven R7 cp.async GEMM compiled in as a
// fallback if tensor-map encode is unavailable. SW128 tensor-map swizzle
// matches the ldsm XOR addressing. 3-stage ring, 2 CTAs/SM.
// ============================================================================

#define INF_   1024
#define OUTF_  1024
#define MTOT   8192
#define KD     6144            // 6 * 1024
#define BM     128
#define BN     128
#define BK     64
#define KT     (KD / BK)       // 96
#define STG    3
#define ASZ    (BM * BK * 2)   // 16384
#define BSZ    (BN * BK * 2)   // 16384
#define STAGEB (ASZ + BSZ)     // 32768
#define HDR    1024
#define SMEMSZ (1024 + HDR + STG * STAGEB)   // align pad + hdr + 96KB
#define SMEMSZ_CA (STG * STAGEB)             // cp.async fallback

__device__ __align__(1024) __half g_A[(size_t)MTOT * KD];   // 96 MB
__device__ __align__(1024) __half g_W[(size_t)OUTF_ * KD];  // 12 MB
__device__ float g_biasp[4096];   // per-(o, i-block) partials of sum_i T0
__device__ float g_bias[1024];    // final bias per o

// ---------------------------------------------------------------------------
// helpers
// ---------------------------------------------------------------------------
__device__ __forceinline__ uint32_t s2u(const void* p) {
    uint32_t a;
    asm("{ .reg .u64 t; cvta.to.shared.u64 t, %1; cvt.u32.u64 %0, t; }"
        : "=r"(a) : "l"(p));
    return a;
}
__device__ __forceinline__ void mbar_init(uint32_t m, uint32_t c) {
    asm volatile("mbarrier.init.shared.b64 [%0], %1;" :: "r"(m), "r"(c) : "memory");
}
__device__ __forceinline__ void mbar_expect(uint32_t m, uint32_t bytes) {
    asm volatile("mbarrier.arrive.expect_tx.shared.b64 _, [%0], %1;"
                 :: "r"(m), "r"(bytes) : "memory");
}
__device__ __forceinline__ void mbar_wait(uint32_t m, uint32_t ph) {
    uint32_t done;
    do {
        asm volatile(
            "{\n\t.reg .pred p;\n\t"
            "mbarrier.try_wait.parity.acquire.cta.shared::cta.b64 p, [%1], %2, 0x989680;\n\t"
            "selp.b32 %0, 1, 0, p;\n\t}"
            : "=r"(done) : "r"(m), "r"(ph) : "memory");
    } while (!done);
}
__device__ __forceinline__ void tma2d(uint32_t dst, const CUtensorMap* m,
                                      int x, int y, uint32_t mbar) {
    asm volatile(
        "cp.async.bulk.tensor.2d.shared::cta.global.tile.mbarrier::complete_tx::bytes "
        "[%0], [%1, {%2, %3}], [%4];"
        :: "r"(dst), "l"(m), "r"(x), "r"(y), "r"(mbar) : "memory");
}
__device__ __forceinline__ void cpasync16(uint32_t dst, const void* src) {
    asm volatile("cp.async.cg.shared.global [%0], [%1], 16;" :: "r"(dst), "l"(src));
}
__device__ __forceinline__ void ldsm4(uint32_t* r, uint32_t a) {
    asm volatile("ldmatrix.sync.aligned.m8n8.x4.shared.b16 {%0,%1,%2,%3}, [%4];"
                 : "=r"(r[0]), "=r"(r[1]), "=r"(r[2]), "=r"(r[3]) : "r"(a));
}
__device__ __forceinline__ void mma16816(float* c, const uint32_t* a, const uint32_t* b) {
    asm volatile(
        "mma.sync.aligned.m16n8k16.row.col.f32.f16.f16.f32 "
        "{%0,%1,%2,%3}, {%4,%5,%6,%7}, {%8,%9}, {%0,%1,%2,%3};"
        : "+f"(c[0]), "+f"(c[1]), "+f"(c[2]), "+f"(c[3])
        : "r"(a[0]), "r"(a[1]), "r"(a[2]), "r"(a[3]), "r"(b[0]), "r"(b[1]));
}

// ---------------------------------------------------------------------------
// build_A: one thread per (m,i). Emits 6 halves [x, hat1..hat5] contiguous.
// ---------------------------------------------------------------------------
__global__ void __launch_bounds__(256) build_A(const float* __restrict__ x) {
    __shared__ __half st[256 * 6];
    int tid = threadIdx.x;
    size_t p = (size_t)blockIdx.x * 256 + tid;
    float xv = x[p];
    float xc = fminf(fmaxf(xv, -1.0f), 1.0f);
    st[tid * 6] = __float2half_rn(xv);
    #pragma unroll
    for (int j = 1; j <= 5; j++) {
        float knot = 0.4f * (float)j - 1.0f;
        float h = fmaxf(0.0f, 1.0f - fabsf(xc - knot) * 2.5f);
        st[tid * 6 + j] = __float2half_rn(h);
    }
    __syncthreads();
    uint4* dst = reinterpret_cast<uint4*>(
        reinterpret_cast<char*>(g_A) + (size_t)blockIdx.x * 3072);
    const uint4* src = reinterpret_cast<const uint4*>(st);
    if (tid < 192) dst[tid] = src[tid];
}

// ---------------------------------------------------------------------------
// build_W: one thread per (o,i). Emits [bw, T1-T0 .. T5-T0]; block-reduces T0.
// ---------------------------------------------------------------------------
__global__ void __launch_bounds__(256) build_W(const float* __restrict__ sw,
                                               const float* __restrict__ bw) {
    __shared__ __half st[256 * 6];
    __shared__ float red[256];
    int tid = threadIdx.x;
    size_t p = (size_t)blockIdx.x * 256 + tid;
    const float4* s4 = reinterpret_cast<const float4*>(sw + p * 12);
    float4 a = s4[0], b = s4[1], c = s4[2];
    float T0 = a.x + a.y + a.z + a.w;
    float T5 = c.x + c.y + c.z + c.w;
    st[tid * 6 + 0] = __float2half_rn(bw[p]);
    st[tid * 6 + 1] = __float2half_rn(b.x - T0);
    st[tid * 6 + 2] = __float2half_rn(b.y - T0);
    st[tid * 6 + 3] = __float2half_rn(b.z - T0);
    st[tid * 6 + 4] = __float2half_rn(b.w - T0);
    st[tid * 6 + 5] = __float2half_rn(T5 - T0);
    red[tid] = T0;
    __syncthreads();
    #pragma unroll
    for (int s = 128; s > 0; s >>= 1) {
        if (tid < s) red[tid] += red[tid + s];
        __syncthreads();
    }
    if (tid == 0) g_biasp[blockIdx.x] = red[0];
    uint4* dst = reinterpret_cast<uint4*>(
        reinterpret_cast<char*>(g_W) + (size_t)blockIdx.x * 3072);
    const uint4* src = reinterpret_cast<const uint4*>(st);
    if (tid < 192) dst[tid] = src[tid];
}

__global__ void sum_bias() {
    int o = blockIdx.x * 256 + threadIdx.x;
    g_bias[o] = g_biasp[o * 4] + g_biasp[o * 4 + 1]
              + g_biasp[o * 4 + 2] + g_biasp[o * 4 + 3];
}

// ---------------------------------------------------------------------------
// shared fragment-load geometry (warp tile 64x32, k16 double buffering)
// ---------------------------------------------------------------------------
#define LDFRAGS(buf, asB_, bsB_, ks_)                                              \
    do {                                                                           \
        _Pragma("unroll")                                                          \
        for (int a_ = 0; a_ < 4; a_++) {                                           \
            int mr_ = wm + a_ * 16 + lr + (mi & 1) * 8;                            \
            int kc_ = (ks_) * 2 + (mi >> 1);                                       \
            ldsm4(aF[buf][a_], (asB_) + mr_ * 128 + ((kc_ ^ (mr_ & 7)) << 4));     \
        }                                                                          \
        _Pragma("unroll")                                                          \
        for (int q_ = 0; q_ < 2; q_++) {                                           \
            int nr_ = wn + q_ * 16 + ((mi >> 1) << 3) + lr;                        \
            int kc_ = (ks_) * 2 + (mi & 1);                                        \
            ldsm4(bF[buf][q_], (bsB_) + nr_ * 128 + ((kc_ ^ (nr_ & 7)) << 4));     \
        }                                                                          \
    } while (0)

#define MMAS_AND_EPILOGUE_DECL()                                                   \
    float acc[4][4][4] = {};

#define DO_KSTEPS(asB, bsB)                                                        \
    do {                                                                           \
        LDFRAGS(0, asB, bsB, 0);                                                   \
        _Pragma("unroll")                                                          \
        for (int ks = 0; ks < 4; ++ks) {                                           \
            if (ks < 3) LDFRAGS((ks + 1) & 1, asB, bsB, ks + 1);                   \
            int bu = ks & 1;                                                       \
            _Pragma("unroll")                                                      \
            for (int a = 0; a < 4; a++)                                            \
                _Pragma("unroll")                                                  \
                for (int b = 0; b < 4; b++)                                        \
                    mma16816(acc[a][b], aF[bu][a], &bF[bu][b >> 1][(b & 1) * 2]);  \
        }                                                                          \
    } while (0)

#define EPILOGUE()                                                                 \
    do {                                                                           \
        int row0 = m0 + wm + (lid >> 2);                                           \
        int col0 = n0 + wn + (lid & 3) * 2;                                        \
        _Pragma("unroll")                                                          \
        for (int b = 0; b < 4; b++) {                                              \
            float bv0 = g_bias[col0 + b * 8];                                      \
            float bv1 = g_bias[col0 + b * 8 + 1];                                  \
            _Pragma("unroll")                                                      \
            for (int a = 0; a < 4; a++) {                                          \
                float* p0 = out + (size_t)(row0 + a * 16) * OUTF_ + col0 + b * 8;  \
                float* p1 = p0 + (size_t)8 * OUTF_;                                \
                *reinterpret_cast<float2*>(p0) =                                   \
                    make_float2(acc[a][b][0] + bv0, acc[a][b][1] + bv1);           \
                *reinterpret_cast<float2*>(p1) =                                   \
                    make_float2(acc[a][b][2] + bv0, acc[a][b][3] + bv1);           \
            }                                                                      \
        }                                                                          \
    } while (0)

// ---------------------------------------------------------------------------
// GEMM (TMA path): 3-stage ring, SW128 tensor maps, mbarrier expect_tx.
// ---------------------------------------------------------------------------
__global__ void __launch_bounds__(256, 2) kan_gemm_tma(
        const __grid_constant__ CUtensorMap tmA,
        const __grid_constant__ CUtensorMap tmB,
        float* __restrict__ out) {
    extern __shared__ unsigned char smem[];
    uint32_t sbA = (s2u(smem) + 1023u) & ~1023u;   // 1024-aligned base
    int tid = threadIdx.x;
    int wid = tid >> 5, lid = tid & 31;
    int n0 = blockIdx.x * BN;
    int m0 = blockIdx.y * BM;

    if (tid == 0) {
        #pragma unroll
        for (int s = 0; s < STG; s++) mbar_init(sbA + 8 * s, 1);
    }
    __syncthreads();
    if (tid == 0) {
        #pragma unroll
        for (int s = 0; s < 2; s++) {        // prologue: stages 0,1
            uint32_t fm = sbA + 8 * s;
            uint32_t ds = sbA + HDR + s * STAGEB;
            mbar_expect(fm, STAGEB);
            tma2d(ds,       &tmA, s * BK, m0, fm);
            tma2d(ds + ASZ, &tmB, s * BK, n0, fm);
        }
    }

    int wm = (wid >> 2) * 64;
    int wn = (wid & 3) * 32;
    int mi = lid >> 3;
    int lr = lid & 7;

    uint32_t aF[2][4][4], bF[2][2][4];
    MMAS_AND_EPILOGUE_DECL();

    int s = 0, phv = 0;     // consumer cursor
    int sp = 2;             // producer's next stage (tid 0 only)
    for (int it = 0; it < KT; ++it) {
        __syncthreads();    // all reads of the stage being reissued are done
        if (tid == 0 && it + 2 < KT) {
            uint32_t fm = sbA + 8 * sp;
            uint32_t ds = sbA + HDR + sp * STAGEB;
            mbar_expect(fm, STAGEB);
            tma2d(ds,       &tmA, (it + 2) * BK, m0, fm);
            tma2d(ds + ASZ, &tmB, (it + 2) * BK, n0, fm);
            sp = (sp == STG - 1) ? 0 : sp + 1;
        }
        mbar_wait(sbA + 8 * s, phv);

        uint32_t asB = sbA + HDR + s * STAGEB;
        uint32_t bsB = asB + ASZ;
        DO_KSTEPS(asB, bsB);
        if (++s == STG) { s = 0; phv ^= 1; }
    }
    EPILOGUE();
}

// ---------------------------------------------------------------------------
// GEMM (cp.async fallback — proven R7 path, 323.6us)
// ---------------------------------------------------------------------------
__global__ void __launch_bounds__(256, 2) kan_gemm_ca(float* __restrict__ out) {
    extern __shared__ unsigned char smem[];
    uint32_t sb = s2u(smem);
    int tid = threadIdx.x;
    int wid = tid >> 5, lid = tid & 31;
    int n0 = blockIdx.x * BN;
    int m0 = blockIdx.y * BM;

    const char* aG = reinterpret_cast<const char*>(g_A) + (size_t)m0 * (KD * 2);
    const char* bG = reinterpret_cast<const char*>(g_W) + (size_t)n0 * (KD * 2);

    #define LOAD_STAGE_CA(s, it)                                                       \
        do {                                                                           \
            uint32_t base_ = sb + (s) * STAGEB;                                        \
            const char* ga_ = aG + (size_t)(it) * 128;                                 \
            const char* gb_ = bG + (size_t)(it) * 128;                                 \
            _Pragma("unroll")                                                          \
            for (int j = 0; j < 4; j++) {                                              \
                int id_ = tid + j * 256;                                               \
                int r_ = id_ >> 3, c_ = id_ & 7;                                       \
                cpasync16(base_ + r_ * 128 + ((c_ ^ (r_ & 7)) << 4),                   \
                          ga_ + (size_t)r_ * (KD * 2) + c_ * 16);                      \
            }                                                                          \
            _Pragma("unroll")                                                          \
            for (int j = 0; j < 4; j++) {                                              \
                int id_ = tid + j * 256;                                               \
                int r_ = id_ >> 3, c_ = id_ & 7;                                       \
                cpasync16(base_ + ASZ + r_ * 128 + ((c_ ^ (r_ & 7)) << 4),             \
                          gb_ + (size_t)r_ * (KD * 2) + c_ * 16);                      \
            }                                                                          \
            asm volatile("cp.async.commit_group;");                                    \
        } while (0)

    int wm = (wid >> 2) * 64;
    int wn = (wid & 3) * 32;
    int mi = lid >> 3;
    int lr = lid & 7;

    uint32_t aF[2][4][4], bF[2][2][4];
    MMAS_AND_EPILOGUE_DECL();

    LOAD_STAGE_CA(0, 0);
    LOAD_STAGE_CA(1, 1);

    int cur = 0, nxt = 2;
    for (int it = 0; it < KT; ++it) {
        asm volatile("cp.async.wait_group 1;");
        __syncthreads();
        if (it + 2 < KT) LOAD_STAGE_CA(nxt, it + 2);
        else             asm volatile("cp.async.commit_group;");

        uint32_t asB = sb + cur * STAGEB;
        uint32_t bsB = asB + ASZ;
        DO_KSTEPS(asB, bsB);
        cur = (cur == STG - 1) ? 0 : cur + 1;
        nxt = (nxt == STG - 1) ? 0 : nxt + 1;
    }
    EPILOGUE();
}

// ---------------------------------------------------------------------------
// host: tensor-map encode via driver entry point (no -lcuda link needed),
// with full error checking and cp.async fallback.
// ---------------------------------------------------------------------------
typedef CUresult (CUDAAPI *PFN_tmEncode)(
    CUtensorMap*, CUtensorMapDataType, cuuint32_t, void*,
    const cuuint64_t*, const cuuint64_t*, const cuuint32_t*, const cuuint32_t*,
    CUtensorMapInterleave, CUtensorMapSwizzle, CUtensorMapL2promotion,
    CUtensorMapFloatOOBfill);

extern "C" void kernel_launch(void* const* d_in, const int* in_sizes, int n_in,
                              void* d_out, int out_size) {
    const float* x  = (const float*)d_in[0];   // (4,2048,1024)
    const float* sw = (const float*)d_in[1];   // (1024,1024,12)
    const float* bw = (const float*)d_in[2];   // (1024,1024)
    float* out = (float*)d_out;                // (4,2048,1024)

    CUtensorMap tmA, tmB;
    int use_tma = 0;
    {
        PFN_tmEncode enc = nullptr;
        cudaDriverEntryPointQueryResult qr = cudaDriverEntryPointSymbolNotFound;
        cudaError_t ge = cudaGetDriverEntryPoint(
            "cuTensorMapEncodeTiled", (void**)&enc, cudaEnableDefault, &qr);
        if (ge == cudaSuccess && qr == cudaDriverEntryPointSuccess && enc) {
            void *pA = nullptr, *pW = nullptr;
            cudaGetSymbolAddress(&pA, g_A);
            cudaGetSymbolAddress(&pW, g_W);
            if (pA && pW) {
                cuuint64_t dimsA[2] = {KD, MTOT};
                cuuint64_t strA[1]  = {KD * 2};
                cuuint32_t boxA[2]  = {BK, BM};
                cuuint32_t el[2]    = {1, 1};
                CUresult r1 = enc(&tmA, CU_TENSOR_MAP_DATA_TYPE_FLOAT16, 2, pA,
                                  dimsA, strA, boxA, el,
                                  CU_TENSOR_MAP_INTERLEAVE_NONE,
                                  CU_TENSOR_MAP_SWIZZLE_128B,
                                  CU_TENSOR_MAP_L2_PROMOTION_L2_128B,
                                  CU_TENSOR_MAP_FLOAT_OOB_FILL_NONE);
                cuuint64_t dimsB[2] = {KD, OUTF_};
                cuuint64_t strB[1]  = {KD * 2};
                cuuint32_t boxB[2]  = {BK, BN};
                CUresult r2 = enc(&tmB, CU_TENSOR_MAP_DATA_TYPE_FLOAT16, 2, pW,
                                  dimsB, strB, boxB, el,
                                  CU_TENSOR_MAP_INTERLEAVE_NONE,
                                  CU_TENSOR_MAP_SWIZZLE_128B,
                                  CU_TENSOR_MAP_L2_PROMOTION_L2_128B,
                                  CU_TENSOR_MAP_FLOAT_OOB_FILL_NONE);
                use_tma = (r1 == CUDA_SUCCESS && r2 == CUDA_SUCCESS);
            }
        }
    }

    cudaFuncSetAttribute(kan_gemm_tma, cudaFuncAttributeMaxDynamicSharedMemorySize, SMEMSZ);
    cudaFuncSetAttribute(kan_gemm_ca,  cudaFuncAttributeMaxDynamicSharedMemorySize, SMEMSZ_CA);

    build_W<<<(OUTF_ * INF_) / 256, 256>>>(sw, bw);
    sum_bias<<<4, 256>>>();
    build_A<<<(MTOT * INF_) / 256, 256>>>(x);
    dim3 grid(OUTF_ / BN, MTOT / BM);   // x = N tile (fast) -> A L2 reuse
    if (use_tma) kan_gemm_tma<<<grid, 256, SMEMSZ>>>(tmA, tmB, out);
    else         kan_gemm_ca<<<grid, 256, SMEMSZ_CA>>>(out);
}